// round 16
// baseline (speedup 1.0000x reference)
#include <cuda_runtime.h>
#include <cuda_fp16.h>
#include <cstdint>

// ---------------------------------------------------------------------------
// Problem constants
// ---------------------------------------------------------------------------
#define R_ROWS 16384
#define N_NODES 512
#define D_DIM 512
#define H_HEADS 256
#define DFF 2048

// Scratch layout (float offsets)
#define OFF_XN   0ull
#define OFF_Q    8388608ull
#define OFF_K    16777216ull
#define OFF_V    25165824ull
#define OFF_AO   33554432ull
#define OFF_X1   41943040ull
#define OFF_HIN  50331648ull
#define OFF_HB   58720256ull
#define OFF_LOG  92274688ull
#define OFF_GB   159383552ull
#define OFF_WQT  159645696ull
#define OFF_WKT  159907840ull
#define OFF_WVT  160169984ull
#define OFF_WOT  160432128ull
#define OFF_W1T  160694272ull
#define OFF_W2T  161742848ull
#define OFF_PM   162791424ull
#define OFF_PS   163315712ull
#define OFF_MINV 163840000ull

__device__ float g_scratch[164102144];

// ===========================================================================
// Helpers
// ===========================================================================
__device__ __forceinline__ uint32_t smem_u32(const void* p) {
    uint32_t a;
    asm("{ .reg .u64 t; cvta.to.shared.u64 t, %1; cvt.u32.u64 %0, t; }"
        : "=r"(a) : "l"(p));
    return a;
}

#define CP_ASYNC16(dst, src) \
    asm volatile("cp.async.cg.shared.global [%0], [%1], 16;" :: "r"(dst), "l"(src))
#define CP_COMMIT() asm volatile("cp.async.commit_group;" ::: "memory")
#define CP_WAIT1()  asm volatile("cp.async.wait_group 1;" ::: "memory")
#define CP_WAIT0()  asm volatile("cp.async.wait_group 0;" ::: "memory")

#define MMA_TF32(d, a0, a1, a2, a3, b0, b1) \
    asm volatile("mma.sync.aligned.m16n8k8.row.col.f32.tf32.tf32.f32 " \
        "{%0,%1,%2,%3}, {%4,%5,%6,%7}, {%8,%9}, {%0,%1,%2,%3};" \
        : "+f"((d)[0]), "+f"((d)[1]), "+f"((d)[2]), "+f"((d)[3]) \
        : "r"(a0), "r"(a1), "r"(a2), "r"(a3), "r"(b0), "r"(b1))

__device__ __forceinline__ float f2tf_f(float x) {
    uint32_t r;
    asm("cvt.rna.tf32.f32 %0, %1;" : "=r"(r) : "f"(x));
    return __uint_as_float(r);
}

// ===========================================================================
// Fused weight pack: all 6 weights in ONE launch (tf32 truncate + fragment
// permute, bitwise identical to per-weight packing).
// ===========================================================================
__global__ __launch_bounds__(256) void pack_all_kernel(
    const float* __restrict__ Wq, const float* __restrict__ Wk,
    const float* __restrict__ Wv, const float* __restrict__ Wo,
    const float* __restrict__ W1, const float* __restrict__ W2,
    float* __restrict__ wqp, float* __restrict__ wkp,
    float* __restrict__ wvp, float* __restrict__ wop,
    float* __restrict__ w1p, float* __restrict__ w2p)
{
    int idx = blockIdx.x * 256 + threadIdx.x;
    if (idx >= 49152 * 32) return;
    int L = idx & 31;
    int g = idx >> 5;

    const float* W;
    float* Wp;
    int bno, K;
    if (g < 16384) {
        int sel = g >> 12;
        bno = g & 4095;
        K = 512;
        W  = (sel == 0) ? Wq  : (sel == 1) ? Wk  : (sel == 2) ? Wv  : Wo;
        Wp = (sel == 0) ? wqp : (sel == 1) ? wkp : (sel == 2) ? wvp : wop;
    } else if (g < 32768) {
        bno = g - 16384; K = 512; W = W1; Wp = w1p;
    } else {
        bno = g - 32768; K = 2048; W = W2; Wp = w2p;
    }
    int kblocks = K >> 3;
    int n8 = bno / kblocks;
    int kc = bno % kblocks;
    int grp = L >> 2, qr = L & 3;
    const float* src = W + (size_t)(n8 * 8 + grp) * K + kc * 8 + qr;
    float v0 = f2tf_f(src[0]);
    float v1 = f2tf_f(src[4]);
    *(float2*)(Wp + (size_t)bno * 64 + L * 2) = make_float2(v0, v1);
}

// ===========================================================================
// 1xTF32 GEMM, A row-major pre-truncated, B fragment-packed (R13 optimum).
// ===========================================================================
#define G1_STAGE_FLOATS 8704
#define G1_SMEM_BYTES  (2 * G1_STAGE_FLOATS * 4)

__global__ __launch_bounds__(256, 2)
void gemm_tc1_kernel(const float* __restrict__ A, const float* __restrict__ Bp,
                     const float* __restrict__ bias, const float* __restrict__ res,
                     float* __restrict__ C, int M, int N, int Kd, int relu, int tout)
{
    extern __shared__ float sm[];
    const int tid  = threadIdx.x;
    const int wid  = tid >> 5;
    const int lane = tid & 31;
    const int grp  = lane >> 2;
    const int qr   = lane & 3;
    const int bm   = blockIdx.y << 7;
    const int bn   = blockIdx.x << 7;
    const uint32_t sbase = smem_u32(sm);

    uint32_t soffA[4];
    const float* gA[4];
#pragma unroll
    for (int i = 0; i < 4; i++) {
        int idx = i * 256 + tid;
        int row = idx >> 3;
        int c4  = idx & 7;
        soffA[i] = (uint32_t)(row * 36 + c4 * 4) * 4u;
        gA[i] = A + (size_t)(bm + row) * Kd + (c4 << 2);
    }
    const int bseg = tid >> 4;
    const int binn = (tid & 15) << 4;
    uint32_t soffB[4];
    const float* gBp[4];
    {
        const int kblocks = Kd >> 3;
        const float* brow = Bp + (size_t)((bn >> 3) + bseg) * kblocks * 64;
#pragma unroll
        for (int j = 0; j < 4; j++) {
            soffB[j] = (uint32_t)(4608 + bseg * 256 + binn + j * 4) * 4u;
            gBp[j] = brow + binn + j * 4;
        }
    }

    const int nc = Kd >> 5;

#pragma unroll
    for (int i = 0; i < 4; i++) CP_ASYNC16(sbase + soffA[i], gA[i]);
#pragma unroll
    for (int j = 0; j < 4; j++) CP_ASYNC16(sbase + soffB[j], gBp[j]);
    CP_COMMIT();

    const int wm = (wid & 3) << 5;
    const int wn = (wid >> 2) << 6;
    const int n8w = wn >> 3;

    float acc[2][8][4];
#pragma unroll
    for (int mt = 0; mt < 2; mt++)
#pragma unroll
        for (int nt = 0; nt < 8; nt++)
#pragma unroll
            for (int r = 0; r < 4; r++) acc[mt][nt][r] = 0.f;

    for (int c = 0; c < nc; c++) {
        CP_WAIT0();
        __syncthreads();
        if (c + 1 < nc) {
            const int k1 = (c + 1) << 5;
            const uint32_t st = sbase + (uint32_t)((c + 1) & 1) * (G1_STAGE_FLOATS * 4u);
#pragma unroll
            for (int i = 0; i < 4; i++)
                CP_ASYNC16(st + soffA[i], gA[i] + k1);
#pragma unroll
            for (int j = 0; j < 4; j++)
                CP_ASYNC16(st + soffB[j], gBp[j] + k1 * 8);
            CP_COMMIT();
        }

        const float* Asb = sm + (c & 1) * G1_STAGE_FLOATS;
        const float* Bb  = Asb + 4608;
#pragma unroll
        for (int ks = 0; ks < 4; ks++) {
            const float* Ac = Asb + ks * 8 + qr;
            uint32_t a_[2][4];
#pragma unroll
            for (int mt = 0; mt < 2; mt++) {
                int r0 = wm + mt * 16 + grp;
                a_[mt][0] = __float_as_uint(Ac[r0 * 36]);
                a_[mt][1] = __float_as_uint(Ac[(r0 + 8) * 36]);
                a_[mt][2] = __float_as_uint(Ac[r0 * 36 + 4]);
                a_[mt][3] = __float_as_uint(Ac[(r0 + 8) * 36 + 4]);
            }
            uint32_t b_[8][2];
#pragma unroll
            for (int nt = 0; nt < 8; nt++) {
                float2 bp = *(const float2*)(Bb + ((n8w + nt) * 4 + ks) * 64 + lane * 2);
                b_[nt][0] = __float_as_uint(bp.x);
                b_[nt][1] = __float_as_uint(bp.y);
            }
#pragma unroll
            for (int mt = 0; mt < 2; mt++)
#pragma unroll
                for (int nt = 0; nt < 8; nt++)
                    MMA_TF32(acc[mt][nt], a_[mt][0], a_[mt][1], a_[mt][2], a_[mt][3],
                             b_[nt][0], b_[nt][1]);
        }
    }

#pragma unroll
    for (int mt = 0; mt < 2; mt++) {
        const int r0 = bm + wm + mt * 16 + grp;
#pragma unroll
        for (int nt = 0; nt < 8; nt++) {
            const int col = bn + wn + nt * 8 + (qr << 1);
            float2 bb = *(const float2*)(bias + col);
            float v0 = acc[mt][nt][0] + bb.x;
            float v1 = acc[mt][nt][1] + bb.y;
            float v2 = acc[mt][nt][2] + bb.x;
            float v3 = acc[mt][nt][3] + bb.y;
            if (relu) {
                v0 = fmaxf(v0, 0.f); v1 = fmaxf(v1, 0.f);
                v2 = fmaxf(v2, 0.f); v3 = fmaxf(v3, 0.f);
            }
            if (res) {
                float2 ra = *(const float2*)(res + (size_t)r0 * N + col);
                float2 rb = *(const float2*)(res + (size_t)(r0 + 8) * N + col);
                v0 += ra.x; v1 += ra.y; v2 += rb.x; v3 += rb.y;
            }
            if (tout) {
                v0 = f2tf_f(v0); v1 = f2tf_f(v1);
                v2 = f2tf_f(v2); v3 = f2tf_f(v3);
            }
            *(float2*)(C + (size_t)r0 * N + col)       = make_float2(v0, v1);
            *(float2*)(C + (size_t)(r0 + 8) * N + col) = make_float2(v2, v3);
        }
    }
}

// ===========================================================================
// Scores (1xTF32): computes per-tile row stats FIRST, then stores
// fp16(exp(l - M_tile)) — half the logits traffic. pm/ps as before.
// ===========================================================================
#define SC_STAGE_FLOATS 9216
#define SC_SMEM_BYTES  (2 * SC_STAGE_FLOATS * 4)

__global__ __launch_bounds__(256, 2)
void tc_scores1_kernel(const float* __restrict__ q, const float* __restrict__ kt,
                       const float* __restrict__ gb, __half* __restrict__ elog,
                       float* __restrict__ pm, float* __restrict__ ps)
{
    extern __shared__ float sm[];
    const int tid  = threadIdx.x;
    const int wid  = tid >> 5;
    const int lane = tid & 31;
    const int grp  = lane >> 2;
    const int qr   = lane & 3;
    const int h  = blockIdx.z;
    const int bt = h >> 3;
    const int kh = h & 7;
    const int bm = blockIdx.y << 7;
    const int bn = blockIdx.x << 7;
    const uint32_t sbase = smem_u32(sm);

    uint32_t soff[4];
    const float* gA[4];
    const float* gB[4];
#pragma unroll
    for (int i = 0; i < 4; i++) {
        int idx = i * 256 + tid;
        int row = idx >> 3;
        int c4  = idx & 7;
        soff[i] = (uint32_t)(row * 36 + c4 * 4) * 4u;
        gA[i] = q  + (size_t)(bt * 512 + bm + row) * 512 + kh * 64 + (c4 << 2);
        gB[i] = kt + (size_t)(bt * 512 + bn + row) * 512 + kh * 64 + (c4 << 2);
    }

#pragma unroll
    for (int i = 0; i < 4; i++) {
        CP_ASYNC16(sbase + soff[i], gA[i]);
        CP_ASYNC16(sbase + 4608u * 4u + soff[i], gB[i]);
    }
    CP_COMMIT();
#pragma unroll
    for (int i = 0; i < 4; i++) {
        CP_ASYNC16(sbase + SC_STAGE_FLOATS * 4u + soff[i], gA[i] + 32);
        CP_ASYNC16(sbase + SC_STAGE_FLOATS * 4u + 4608u * 4u + soff[i], gB[i] + 32);
    }
    CP_COMMIT();

    const int wm = (wid & 3) << 5;
    const int wn = (wid >> 2) << 6;

    float acc[2][8][4];
#pragma unroll
    for (int mt = 0; mt < 2; mt++)
#pragma unroll
        for (int nt = 0; nt < 8; nt++)
#pragma unroll
            for (int r = 0; r < 4; r++) acc[mt][nt][r] = 0.f;

#pragma unroll
    for (int c = 0; c < 2; c++) {
        if (c == 0) { CP_WAIT1(); } else { CP_WAIT0(); }
        __syncthreads();
        const float* Asb = sm + c * SC_STAGE_FLOATS;
        const float* Bsb = Asb + 4608;
#pragma unroll
        for (int ks = 0; ks < 4; ks++) {
            const float* Ac = Asb + ks * 8 + qr;
            const float* Bc = Bsb + ks * 8 + qr;
            uint32_t a_[2][4];
#pragma unroll
            for (int mt = 0; mt < 2; mt++) {
                int r0 = wm + mt * 16 + grp;
                a_[mt][0] = __float_as_uint(Ac[r0 * 36]);
                a_[mt][1] = __float_as_uint(Ac[(r0 + 8) * 36]);
                a_[mt][2] = __float_as_uint(Ac[r0 * 36 + 4]);
                a_[mt][3] = __float_as_uint(Ac[(r0 + 8) * 36 + 4]);
            }
            uint32_t b_[8][2];
#pragma unroll
            for (int nt = 0; nt < 8; nt++) {
                int rn = wn + nt * 8 + grp;
                b_[nt][0] = __float_as_uint(Bc[rn * 36]);
                b_[nt][1] = __float_as_uint(Bc[rn * 36 + 4]);
            }
#pragma unroll
            for (int mt = 0; mt < 2; mt++)
#pragma unroll
                for (int nt = 0; nt < 8; nt++)
                    MMA_TF32(acc[mt][nt], a_[mt][0], a_[mt][1], a_[mt][2], a_[mt][3],
                             b_[nt][0], b_[nt][1]);
        }
    }

    // finalize logits into acc (scale + graph bias), no store yet
#pragma unroll
    for (int mt = 0; mt < 2; mt++) {
        const int gi = bm + wm + mt * 16 + grp;
#pragma unroll
        for (int nt = 0; nt < 8; nt++) {
            const int gj = bn + wn + nt * 8 + (qr << 1);
            float2 g0 = *(const float2*)(gb + (size_t)gi * 512 + gj);
            float2 g1 = *(const float2*)(gb + (size_t)(gi + 8) * 512 + gj);
            acc[mt][nt][0] = fmaf(acc[mt][nt][0], 0.125f, g0.x);
            acc[mt][nt][1] = fmaf(acc[mt][nt][1], 0.125f, g0.y);
            acc[mt][nt][2] = fmaf(acc[mt][nt][2], 0.125f, g1.x);
            acc[mt][nt][3] = fmaf(acc[mt][nt][3], 0.125f, g1.y);
        }
    }

    // per-tile row stats: per-nw partials -> smem merge -> M,S
    __syncthreads();
    float* smm = sm;          // [2][128]
    float* sms = sm + 256;    // [2][128]
    float* smM = sm + 512;    // [128] merged row max
    const int nw = wid >> 2;
#pragma unroll
    for (int mt = 0; mt < 2; mt++) {
#pragma unroll
        for (int half = 0; half < 2; half++) {
            float mx = -3.0e38f;
#pragma unroll
            for (int nt = 0; nt < 8; nt++)
                mx = fmaxf(mx, fmaxf(acc[mt][nt][half * 2], acc[mt][nt][half * 2 + 1]));
            mx = fmaxf(mx, __shfl_xor_sync(0xffffffffu, mx, 1));
            mx = fmaxf(mx, __shfl_xor_sync(0xffffffffu, mx, 2));
            float s = 0.f;
#pragma unroll
            for (int nt = 0; nt < 8; nt++) {
                s += __expf(acc[mt][nt][half * 2]     - mx);
                s += __expf(acc[mt][nt][half * 2 + 1] - mx);
            }
            s += __shfl_xor_sync(0xffffffffu, s, 1);
            s += __shfl_xor_sync(0xffffffffu, s, 2);
            if (qr == 0) {
                int r = (wid & 3) * 32 + mt * 16 + half * 8 + grp;
                smm[nw * 128 + r] = mx;
                sms[nw * 128 + r] = s;
            }
        }
    }
    __syncthreads();
    if (tid < 128) {
        float m0 = smm[tid], m1 = smm[128 + tid];
        float s0 = sms[tid], s1 = sms[128 + tid];
        float M = fmaxf(m0, m1);
        float S = s0 * __expf(m0 - M) + s1 * __expf(m1 - M);
        size_t pidx = ((size_t)h * 4 + blockIdx.x) * 512 + bm + tid;
        pm[pidx] = M;
        ps[pidx] = S;
        smM[tid] = M;
    }
    __syncthreads();

    // store fp16(exp(l - M_tile))
    __half* Lh = elog + (size_t)h * 512 * 512;
#pragma unroll
    for (int mt = 0; mt < 2; mt++) {
        const int li = wm + mt * 16 + grp;
        const float M0 = smM[li];
        const float M1 = smM[li + 8];
        const int gi = bm + li;
#pragma unroll
        for (int nt = 0; nt < 8; nt++) {
            const int gj = bn + wn + nt * 8 + (qr << 1);
            __half2 e0 = __floats2half2_rn(__expf(acc[mt][nt][0] - M0),
                                           __expf(acc[mt][nt][1] - M0));
            __half2 e1 = __floats2half2_rn(__expf(acc[mt][nt][2] - M1),
                                           __expf(acc[mt][nt][3] - M1));
            *(__half2*)(Lh + (size_t)gi * 512 + gj)       = e0;
            *(__half2*)(Lh + (size_t)(gi + 8) * 512 + gj) = e1;
        }
    }
}

// ===========================================================================
// Row stat merge
// ===========================================================================
__global__ __launch_bounds__(256) void rowstat_kernel(
    const float* __restrict__ pm, const float* __restrict__ ps,
    float2* __restrict__ minv)
{
    int idx = blockIdx.x * 256 + threadIdx.x;
    if (idx >= H_HEADS * 512) return;
    int h = idx >> 9, row = idx & 511;
    float m[4], s[4];
#pragma unroll
    for (int jt = 0; jt < 4; jt++) {
        size_t p = ((size_t)h * 4 + jt) * 512 + row;
        m[jt] = pm[p]; s[jt] = ps[p];
    }
    float M = fmaxf(fmaxf(m[0], m[1]), fmaxf(m[2], m[3]));
    float S = s[0] * __expf(m[0] - M) + s[1] * __expf(m[1] - M)
            + s[2] * __expf(m[2] - M) + s[3] * __expf(m[3] - M);
    minv[idx] = make_float2(M, 1.0f / S);
}

// ===========================================================================
// AV (1xTF32): P staged from fp16 exp-values with per-(row, jtile) scale
//   P = tf32( e * exp(M_tile - M_row) * invS ).  ao truncated.
// ===========================================================================
#define AV1_STAGE_FLOATS 6912
#define AV1_SMEM_BYTES  (2 * AV1_STAGE_FLOATS * 4)

__global__ __launch_bounds__(256, 2)
void tc_av1_kernel(const __half* __restrict__ elog, const float* __restrict__ vt,
                   const float* __restrict__ pm, const float2* __restrict__ minv,
                   float* __restrict__ out)
{
    extern __shared__ float sm[];
    const int tid  = threadIdx.x;
    const int wid  = tid >> 5;
    const int lane = tid & 31;
    const int grp  = lane >> 2;
    const int qr   = lane & 3;
    const int h  = blockIdx.y;
    const int bt = h >> 3;
    const int kh = h & 7;
    const int bm = blockIdx.x << 7;

    int arow[4], ac4[4];
    float2 mi[4];
#pragma unroll
    for (int i = 0; i < 4; i++) {
        int idx = i * 256 + tid;
        arow[i] = idx >> 3;
        ac4[i]  = (idx & 7) << 2;
        mi[i] = minv[(size_t)h * 512 + bm + arow[i]];
    }
    int bk_[2], bn4[2];
#pragma unroll
    for (int i = 0; i < 2; i++) {
        int idx = i * 256 + tid;
        bk_[i] = idx >> 4;
        bn4[i] = (idx & 15) << 2;
    }

    const __half* Abase = elog + (size_t)(h * 512 + bm) * 512;
    const float* Vbase = vt + (size_t)(bt * 512) * 512 + kh * 64;

    float sc[4];
#pragma unroll
    for (int i = 0; i < 4; i++) {
        float Mt = pm[((size_t)h * 4 + 0) * 512 + bm + arow[i]];
        sc[i] = __expf(Mt - mi[i].x) * mi[i].y;
    }

    uint2 rau[4];
    float4 rb[2];
#pragma unroll
    for (int i = 0; i < 4; i++)
        rau[i] = *(const uint2*)(Abase + (size_t)arow[i] * 512 + ac4[i]);
#pragma unroll
    for (int i = 0; i < 2; i++)
        rb[i] = *(const float4*)(Vbase + (size_t)bk_[i] * 512 + bn4[i]);

    const int wm = (wid & 3) << 5;
    const int wn = (wid >> 2) << 5;

    float acc[2][4][4];
#pragma unroll
    for (int mt = 0; mt < 2; mt++)
#pragma unroll
        for (int nt = 0; nt < 4; nt++)
#pragma unroll
            for (int r = 0; r < 4; r++) acc[mt][nt][r] = 0.f;

    for (int c = 0; c < 16; c++) {
        float* Asb = sm + (c & 1) * AV1_STAGE_FLOATS;
        float* Bsb = Asb + 4608;
#pragma unroll
        for (int i = 0; i < 4; i++) {
            __half2 hA = *reinterpret_cast<const __half2*>(&rau[i].x);
            __half2 hB = *reinterpret_cast<const __half2*>(&rau[i].y);
            float2 fA = __half22float2(hA);
            float2 fB = __half22float2(hB);
            float* p = Asb + arow[i] * 36 + ac4[i];
            p[0] = f2tf_f(fA.x * sc[i]);
            p[1] = f2tf_f(fA.y * sc[i]);
            p[2] = f2tf_f(fB.x * sc[i]);
            p[3] = f2tf_f(fB.y * sc[i]);
        }
#pragma unroll
        for (int i = 0; i < 2; i++) {
            Bsb[(bn4[i] + 0) * 36 + bk_[i]] = rb[i].x;
            Bsb[(bn4[i] + 1) * 36 + bk_[i]] = rb[i].y;
            Bsb[(bn4[i] + 2) * 36 + bk_[i]] = rb[i].z;
            Bsb[(bn4[i] + 3) * 36 + bk_[i]] = rb[i].w;
        }
        __syncthreads();
        if (c + 1 < 16) {
            const int k1 = (c + 1) << 5;
#pragma unroll
            for (int i = 0; i < 4; i++)
                rau[i] = *(const uint2*)(Abase + (size_t)arow[i] * 512 + k1 + ac4[i]);
#pragma unroll
            for (int i = 0; i < 2; i++)
                rb[i] = *(const float4*)(Vbase + (size_t)(k1 + bk_[i]) * 512 + bn4[i]);
            if (((c + 1) & 3) == 0) {
                const int jt = (c + 1) >> 2;
#pragma unroll
                for (int i = 0; i < 4; i++) {
                    float Mt = pm[((size_t)h * 4 + jt) * 512 + bm + arow[i]];
                    sc[i] = __expf(Mt - mi[i].x) * mi[i].y;
                }
            }
        }
#pragma unroll
        for (int ks = 0; ks < 4; ks++) {
            const float* Ac = Asb + ks * 8 + qr;
            const float* Bc = Bsb + ks * 8 + qr;
            uint32_t a_[2][4];
#pragma unroll
            for (int mt = 0; mt < 2; mt++) {
                int r0 = wm + mt * 16 + grp;
                a_[mt][0] = __float_as_uint(Ac[r0 * 36]);
                a_[mt][1] = __float_as_uint(Ac[(r0 + 8) * 36]);
                a_[mt][2] = __float_as_uint(Ac[r0 * 36 + 4]);
                a_[mt][3] = __float_as_uint(Ac[(r0 + 8) * 36 + 4]);
            }
            uint32_t b_[4][2];
#pragma unroll
            for (int nt = 0; nt < 4; nt++) {
                int rn = wn + nt * 8 + grp;
                b_[nt][0] = __float_as_uint(Bc[rn * 36]);
                b_[nt][1] = __float_as_uint(Bc[rn * 36 + 4]);
            }
#pragma unroll
            for (int mt = 0; mt < 2; mt++)
#pragma unroll
                for (int nt = 0; nt < 4; nt++)
                    MMA_TF32(acc[mt][nt], a_[mt][0], a_[mt][1], a_[mt][2], a_[mt][3],
                             b_[nt][0], b_[nt][1]);
        }
        __syncthreads();
    }

#pragma unroll
    for (int mt = 0; mt < 2; mt++) {
        const int r0 = bt * 512 + bm + wm + mt * 16 + grp;
#pragma unroll
        for (int nt = 0; nt < 4; nt++) {
            const int col = kh * 64 + wn + nt * 8 + (qr << 1);
            *(float2*)(out + (size_t)r0 * 512 + col) =
                make_float2(f2tf_f(acc[mt][nt][0]), f2tf_f(acc[mt][nt][1]));
            *(float2*)(out + (size_t)(r0 + 8) * 512 + col) =
                make_float2(f2tf_f(acc[mt][nt][2]), f2tf_f(acc[mt][nt][3]));
        }
    }
}

// ---------------------------------------------------------------------------
// Graph bias precompute
// ---------------------------------------------------------------------------
__global__ __launch_bounds__(256) void bias_kernel(
    const float* __restrict__ E, const float* __restrict__ lap,
    const float* __restrict__ alphap, const float* __restrict__ betap,
    float* __restrict__ gb)
{
    __shared__ __align__(16) float ei[64];
    __shared__ float reda[8];
    __shared__ float redb[8];
    int i = blockIdx.x;
    int tid = threadIdx.x;
    if (tid < 16) ((float4*)ei)[tid] = ((const float4*)(E + (size_t)i * 64))[tid];
    __syncthreads();

    int j0 = tid, j1 = tid + 256;
    const float* e0 = E + (size_t)j0 * 64;
    const float* e1 = E + (size_t)j1 * 64;
    float r0 = 0.f, r1 = 0.f;
#pragma unroll
    for (int e = 0; e < 64; e += 4) {
        float4 a = *(const float4*)(ei + e);
        float4 u = *(const float4*)(e0 + e);
        float4 w = *(const float4*)(e1 + e);
        r0 += a.x * u.x + a.y * u.y + a.z * u.z + a.w * u.w;
        r1 += a.x * w.x + a.y * w.y + a.z * w.z + a.w * w.w;
    }
    r0 = fmaxf(r0, 0.f);
    r1 = fmaxf(r1, 0.f);

    float mx = fmaxf(r0, r1);
#pragma unroll
    for (int o = 16; o; o >>= 1) mx = fmaxf(mx, __shfl_xor_sync(0xffffffffu, mx, o));
    if ((tid & 31) == 0) reda[tid >> 5] = mx;
    __syncthreads();
    mx = fmaxf(fmaxf(fmaxf(reda[0], reda[1]), fmaxf(reda[2], reda[3])),
               fmaxf(fmaxf(reda[4], reda[5]), fmaxf(reda[6], reda[7])));

    float ex0 = __expf(r0 - mx), ex1 = __expf(r1 - mx);
    float s = ex0 + ex1;
#pragma unroll
    for (int o = 16; o; o >>= 1) s += __shfl_xor_sync(0xffffffffu, s, o);
    if ((tid & 31) == 0) redb[tid >> 5] = s;
    __syncthreads();
    s = redb[0] + redb[1] + redb[2] + redb[3] + redb[4] + redb[5] + redb[6] + redb[7];
    float inv = 1.0f / s;

    float alpha = *alphap, beta = *betap;
    float lp0 = lap[(size_t)i * 512 + j0];
    float lp1 = lap[(size_t)i * 512 + j1];
    float m0 = (lp0 != 0.f) ? 0.f : -1e9f;
    float m1 = (lp1 != 0.f) ? 0.f : -1e9f;
    gb[(size_t)i * 512 + j0] = alpha * ex0 * inv + beta * lp0 + m0;
    gb[(size_t)i * 512 + j1] = alpha * ex1 * inv + beta * lp1 + m1;
}

// ---------------------------------------------------------------------------
// LayerNorm over D=512, one warp per row, tf32-truncated output.
// ---------------------------------------------------------------------------
__global__ __launch_bounds__(256) void ln_kernel(
    const float* __restrict__ X, const float* __restrict__ g,
    const float* __restrict__ b, float* __restrict__ Y, int rows)
{
    int gw = (blockIdx.x * 256 + threadIdx.x) >> 5;
    if (gw >= rows) return;
    int lane = threadIdx.x & 31;
    const float* xr = X + (size_t)gw * 512;
    float* yr = Y + (size_t)gw * 512;
    float4 v[4];
    float s = 0.f, ss = 0.f;
#pragma unroll
    for (int w = 0; w < 4; w++) {
        v[w] = *(const float4*)(xr + w * 128 + lane * 4);
        s += v[w].x + v[w].y + v[w].z + v[w].w;
        ss += v[w].x * v[w].x + v[w].y * v[w].y + v[w].z * v[w].z + v[w].w * v[w].w;
    }
#pragma unroll
    for (int o = 16; o; o >>= 1) {
        s += __shfl_xor_sync(0xffffffffu, s, o);
        ss += __shfl_xor_sync(0xffffffffu, ss, o);
    }
    float mean = s * (1.0f / 512.0f);
    float var = ss * (1.0f / 512.0f) - mean * mean;
    float rstd = rsqrtf(var + 1e-5f);
#pragma unroll
    for (int w = 0; w < 4; w++) {
        int c = w * 128 + lane * 4;
        float4 gg = *(const float4*)(g + c);
        float4 bb = *(const float4*)(b + c);
        float4 o;
        o.x = f2tf_f((v[w].x - mean) * rstd * gg.x + bb.x);
        o.y = f2tf_f((v[w].y - mean) * rstd * gg.y + bb.y);
        o.z = f2tf_f((v[w].z - mean) * rstd * gg.z + bb.z);
        o.w = f2tf_f((v[w].w - mean) * rstd * gg.w + bb.w);
        *(float4*)(yr + c) = o;
    }
}

// ---------------------------------------------------------------------------
// Host launcher
// ---------------------------------------------------------------------------
extern "C" void kernel_launch(void* const* d_in, const int* in_sizes, int n_in,
                              void* d_out, int out_size)
{
    const float* x    = (const float*)d_in[0];
    const float* lap  = (const float*)d_in[1];
    const float* emb  = (const float*)d_in[2];
    const float* Wq   = (const float*)d_in[3];
    const float* bq   = (const float*)d_in[4];
    const float* Wk   = (const float*)d_in[5];
    const float* bk   = (const float*)d_in[6];
    const float* Wv   = (const float*)d_in[7];
    const float* bv   = (const float*)d_in[8];
    const float* ln1g = (const float*)d_in[9];
    const float* ln1b = (const float*)d_in[10];
    const float* ln2g = (const float*)d_in[11];
    const float* ln2b = (const float*)d_in[12];
    const float* alpha = (const float*)d_in[13];
    const float* beta  = (const float*)d_in[14];
    const float* Wo   = (const float*)d_in[15];
    const float* bo   = (const float*)d_in[16];
    const float* W1   = (const float*)d_in[17];
    const float* b1   = (const float*)d_in[18];
    const float* W2   = (const float*)d_in[19];
    const float* b2   = (const float*)d_in[20];
    float* out = (float*)d_out;

    float* base = nullptr;
    cudaGetSymbolAddress((void**)&base, g_scratch);
    float* xn     = base + OFF_XN;
    float* q      = base + OFF_Q;
    float* kbuf   = base + OFF_K;
    float* vbuf   = base + OFF_V;
    float* ao     = base + OFF_AO;
    float* x1     = base + OFF_X1;
    float* hin    = base + OFF_HIN;
    float* hbuf   = base + OFF_HB;
    __half* elog  = (__half*)(base + OFF_LOG);
    float* gb     = base + OFF_GB;
    float* wqp = base + OFF_WQT;
    float* wkp = base + OFF_WKT;
    float* wvp = base + OFF_WVT;
    float* wop = base + OFF_WOT;
    float* w1p = base + OFF_W1T;
    float* w2p = base + OFF_W2T;
    float* pm  = base + OFF_PM;
    float* ps  = base + OFF_PS;
    float2* minv = (float2*)(base + OFF_MINV);

    static bool attr_done = false;
    if (!attr_done) {
        cudaFuncSetAttribute(gemm_tc1_kernel,
                             cudaFuncAttributeMaxDynamicSharedMemorySize, G1_SMEM_BYTES);
        cudaFuncSetAttribute(tc_scores1_kernel,
                             cudaFuncAttributeMaxDynamicSharedMemorySize, SC_SMEM_BYTES);
        cudaFuncSetAttribute(tc_av1_kernel,
                             cudaFuncAttributeMaxDynamicSharedMemorySize, AV1_SMEM_BYTES);
        attr_done = true;
    }

    // 0. all-weight tf32 truncate + fragment pack in one launch
    pack_all_kernel<<<6144, 256>>>(Wq, Wk, Wv, Wo, W1, W2,
                                   wqp, wkp, wvp, wop, w1p, w2p);

    // 1. graph bias
    bias_kernel<<<512, 256>>>(emb, lap, alpha, beta, gb);

    // 2. LN1 (tf32-truncated)
    ln_kernel<<<R_ROWS / 8, 256>>>(x, ln1g, ln1b, xn, R_ROWS);

    // 3. QKV projections (1x, packed-B; truncated outputs)
    dim3 gq(D_DIM / 128, R_ROWS / 128);
    gemm_tc1_kernel<<<gq, 256, G1_SMEM_BYTES>>>(
        xn, wqp, bq, nullptr, q,    R_ROWS, D_DIM, D_DIM, 0, 1);
    gemm_tc1_kernel<<<gq, 256, G1_SMEM_BYTES>>>(
        xn, wkp, bk, nullptr, kbuf, R_ROWS, D_DIM, D_DIM, 0, 1);
    gemm_tc1_kernel<<<gq, 256, G1_SMEM_BYTES>>>(
        xn, wvp, bv, nullptr, vbuf, R_ROWS, D_DIM, D_DIM, 0, 1);

    // 4. scores + bias + fused stats, fp16 exp-logits (half the traffic)
    tc_scores1_kernel<<<dim3(4, 4, H_HEADS), 256, SC_SMEM_BYTES>>>(
        q, kbuf, gb, elog, pm, ps);

    // 5. merge row stats
    rowstat_kernel<<<512, 256>>>(pm, ps, minv);

    // 6. attn @ V with per-(row,jtile) rescale from fp16 exp-logits
    tc_av1_kernel<<<dim3(4, H_HEADS), 256, AV1_SMEM_BYTES>>>(
        elog, vbuf, pm, minv, ao);

    // 7. output projection + residual (1x, packed-B)
    gemm_tc1_kernel<<<gq, 256, G1_SMEM_BYTES>>>(
        ao, wop, bo, x, x1, R_ROWS, D_DIM, D_DIM, 0, 0);

    // 8. LN2 (tf32-truncated)
    ln_kernel<<<R_ROWS / 8, 256>>>(x1, ln2g, ln2b, hin, R_ROWS);

    // 9. FF up (1x, packed-B, relu, truncated output)
    gemm_tc1_kernel<<<dim3(DFF / 128, R_ROWS / 128), 256, G1_SMEM_BYTES>>>(
        hin, w1p, b1, nullptr, hbuf, R_ROWS, DFF, D_DIM, 1, 1);

    // 10. FF down + residual (1x, packed-B)
    gemm_tc1_kernel<<<dim3(D_DIM / 128, R_ROWS / 128), 256, G1_SMEM_BYTES>>>(
        hbuf, w2p, b2, x1, out, R_ROWS, D_DIM, DFF, 0, 0);
}

// round 17
// speedup vs baseline: 1.0384x; 1.0384x over previous
#include <cuda_runtime.h>
#include <cstdint>

// ---------------------------------------------------------------------------
// Problem constants
// ---------------------------------------------------------------------------
#define R_ROWS 16384
#define N_NODES 512
#define D_DIM 512
#define H_HEADS 256
#define DFF 2048

// Scratch layout (float offsets)
#define OFF_XN   0ull
#define OFF_Q    8388608ull
#define OFF_K    16777216ull
#define OFF_V    25165824ull
#define OFF_AO   33554432ull
#define OFF_X1   41943040ull
#define OFF_HIN  50331648ull
#define OFF_HB   58720256ull
#define OFF_LOG  92274688ull
#define OFF_GB   159383552ull
#define OFF_WQT  159645696ull
#define OFF_WKT  159907840ull
#define OFF_WVT  160169984ull
#define OFF_WOT  160432128ull
#define OFF_W1T  160694272ull
#define OFF_W2T  161742848ull
#define OFF_PM   162791424ull
#define OFF_PS   163315712ull
#define OFF_MINV 163840000ull

__device__ float g_scratch[164102144];

// ===========================================================================
// Helpers
// ===========================================================================
__device__ __forceinline__ uint32_t smem_u32(const void* p) {
    uint32_t a;
    asm("{ .reg .u64 t; cvta.to.shared.u64 t, %1; cvt.u32.u64 %0, t; }"
        : "=r"(a) : "l"(p));
    return a;
}

#define CP_ASYNC16(dst, src) \
    asm volatile("cp.async.cg.shared.global [%0], [%1], 16;" :: "r"(dst), "l"(src))
#define CP_COMMIT() asm volatile("cp.async.commit_group;" ::: "memory")
#define CP_WAIT1()  asm volatile("cp.async.wait_group 1;" ::: "memory")
#define CP_WAIT0()  asm volatile("cp.async.wait_group 0;" ::: "memory")

#define MMA_TF32(d, a0, a1, a2, a3, b0, b1) \
    asm volatile("mma.sync.aligned.m16n8k8.row.col.f32.tf32.tf32.f32 " \
        "{%0,%1,%2,%3}, {%4,%5,%6,%7}, {%8,%9}, {%0,%1,%2,%3};" \
        : "+f"((d)[0]), "+f"((d)[1]), "+f"((d)[2]), "+f"((d)[3]) \
        : "r"(a0), "r"(a1), "r"(a2), "r"(a3), "r"(b0), "r"(b1))

__device__ __forceinline__ float f2tf_f(float x) {
    uint32_t r;
    asm("cvt.rna.tf32.f32 %0, %1;" : "=r"(r) : "f"(x));
    return __uint_as_float(r);
}

// ===========================================================================
// Fused weight pack: all 6 weights in ONE launch (tf32 truncate + fragment
// permute).
// ===========================================================================
__global__ __launch_bounds__(256) void pack_all_kernel(
    const float* __restrict__ Wq, const float* __restrict__ Wk,
    const float* __restrict__ Wv, const float* __restrict__ Wo,
    const float* __restrict__ W1, const float* __restrict__ W2,
    float* __restrict__ wqp, float* __restrict__ wkp,
    float* __restrict__ wvp, float* __restrict__ wop,
    float* __restrict__ w1p, float* __restrict__ w2p)
{
    int idx = blockIdx.x * 256 + threadIdx.x;
    if (idx >= 49152 * 32) return;
    int L = idx & 31;
    int g = idx >> 5;

    const float* W;
    float* Wp;
    int bno, K;
    if (g < 16384) {
        int sel = g >> 12;
        bno = g & 4095;
        K = 512;
        W  = (sel == 0) ? Wq  : (sel == 1) ? Wk  : (sel == 2) ? Wv  : Wo;
        Wp = (sel == 0) ? wqp : (sel == 1) ? wkp : (sel == 2) ? wvp : wop;
    } else if (g < 32768) {
        bno = g - 16384; K = 512; W = W1; Wp = w1p;
    } else {
        bno = g - 32768; K = 2048; W = W2; Wp = w2p;
    }
    int kblocks = K >> 3;
    int n8 = bno / kblocks;
    int kc = bno % kblocks;
    int grp = L >> 2, qr = L & 3;
    const float* src = W + (size_t)(n8 * 8 + grp) * K + kc * 8 + qr;
    float v0 = f2tf_f(src[0]);
    float v1 = f2tf_f(src[4]);
    *(float2*)(Wp + (size_t)bno * 64 + L * 2) = make_float2(v0, v1);
}

// ===========================================================================
// Shared GEMM mainloop body (1xTF32, A row-major pre-truncated,
// B fragment-packed). Used by the generic GEMM and the merged-QKV kernel.
// ===========================================================================
#define G1_STAGE_FLOATS 8704
#define G1_SMEM_BYTES  (2 * G1_STAGE_FLOATS * 4)

__device__ __forceinline__ void gemm_core(
    float* sm, const float* A, const float* Bp,
    int bm, int bn, int Kd, float acc[2][8][4],
    int tid, int wid, int lane, int grp, int qr)
{
    const uint32_t sbase = smem_u32(sm);

    uint32_t soffA[4];
    const float* gA[4];
#pragma unroll
    for (int i = 0; i < 4; i++) {
        int idx = i * 256 + tid;
        int row = idx >> 3;
        int c4  = idx & 7;
        soffA[i] = (uint32_t)(row * 36 + c4 * 4) * 4u;
        gA[i] = A + (size_t)(bm + row) * Kd + (c4 << 2);
    }
    const int bseg = tid >> 4;
    const int binn = (tid & 15) << 4;
    uint32_t soffB[4];
    const float* gBp[4];
    {
        const int kblocks = Kd >> 3;
        const float* brow = Bp + (size_t)((bn >> 3) + bseg) * kblocks * 64;
#pragma unroll
        for (int j = 0; j < 4; j++) {
            soffB[j] = (uint32_t)(4608 + bseg * 256 + binn + j * 4) * 4u;
            gBp[j] = brow + binn + j * 4;
        }
    }

    const int nc = Kd >> 5;

#pragma unroll
    for (int i = 0; i < 4; i++) CP_ASYNC16(sbase + soffA[i], gA[i]);
#pragma unroll
    for (int j = 0; j < 4; j++) CP_ASYNC16(sbase + soffB[j], gBp[j]);
    CP_COMMIT();

    const int wm = (wid & 3) << 5;
    const int wn = (wid >> 2) << 6;
    const int n8w = wn >> 3;

    for (int c = 0; c < nc; c++) {
        CP_WAIT0();
        __syncthreads();
        if (c + 1 < nc) {
            const int k1 = (c + 1) << 5;
            const uint32_t st = sbase + (uint32_t)((c + 1) & 1) * (G1_STAGE_FLOATS * 4u);
#pragma unroll
            for (int i = 0; i < 4; i++)
                CP_ASYNC16(st + soffA[i], gA[i] + k1);
#pragma unroll
            for (int j = 0; j < 4; j++)
                CP_ASYNC16(st + soffB[j], gBp[j] + k1 * 8);
            CP_COMMIT();
        }

        const float* Asb = sm + (c & 1) * G1_STAGE_FLOATS;
        const float* Bb  = Asb + 4608;
#pragma unroll
        for (int ks = 0; ks < 4; ks++) {
            const float* Ac = Asb + ks * 8 + qr;
            uint32_t a_[2][4];
#pragma unroll
            for (int mt = 0; mt < 2; mt++) {
                int r0 = wm + mt * 16 + grp;
                a_[mt][0] = __float_as_uint(Ac[r0 * 36]);
                a_[mt][1] = __float_as_uint(Ac[(r0 + 8) * 36]);
                a_[mt][2] = __float_as_uint(Ac[r0 * 36 + 4]);
                a_[mt][3] = __float_as_uint(Ac[(r0 + 8) * 36 + 4]);
            }
            uint32_t b_[8][2];
#pragma unroll
            for (int nt = 0; nt < 8; nt++) {
                float2 bp = *(const float2*)(Bb + ((n8w + nt) * 4 + ks) * 64 + lane * 2);
                b_[nt][0] = __float_as_uint(bp.x);
                b_[nt][1] = __float_as_uint(bp.y);
            }
#pragma unroll
            for (int mt = 0; mt < 2; mt++)
#pragma unroll
                for (int nt = 0; nt < 8; nt++)
                    MMA_TF32(acc[mt][nt], a_[mt][0], a_[mt][1], a_[mt][2], a_[mt][3],
                             b_[nt][0], b_[nt][1]);
        }
    }
}

__device__ __forceinline__ void gemm_epilogue(
    float acc[2][8][4], const float* bias, const float* res, float* C,
    int bm, int bn, int N, int relu, int tout,
    int wid, int grp, int qr)
{
    const int wm = (wid & 3) << 5;
    const int wn = (wid >> 2) << 6;
#pragma unroll
    for (int mt = 0; mt < 2; mt++) {
        const int r0 = bm + wm + mt * 16 + grp;
#pragma unroll
        for (int nt = 0; nt < 8; nt++) {
            const int col = bn + wn + nt * 8 + (qr << 1);
            float2 bb = *(const float2*)(bias + col);
            float v0 = acc[mt][nt][0] + bb.x;
            float v1 = acc[mt][nt][1] + bb.y;
            float v2 = acc[mt][nt][2] + bb.x;
            float v3 = acc[mt][nt][3] + bb.y;
            if (relu) {
                v0 = fmaxf(v0, 0.f); v1 = fmaxf(v1, 0.f);
                v2 = fmaxf(v2, 0.f); v3 = fmaxf(v3, 0.f);
            }
            if (res) {
                float2 ra = *(const float2*)(res + (size_t)r0 * N + col);
                float2 rb = *(const float2*)(res + (size_t)(r0 + 8) * N + col);
                v0 += ra.x; v1 += ra.y; v2 += rb.x; v3 += rb.y;
            }
            if (tout) {
                v0 = f2tf_f(v0); v1 = f2tf_f(v1);
                v2 = f2tf_f(v2); v3 = f2tf_f(v3);
            }
            *(float2*)(C + (size_t)r0 * N + col)       = make_float2(v0, v1);
            *(float2*)(C + (size_t)(r0 + 8) * N + col) = make_float2(v2, v3);
        }
    }
}

// Generic GEMM (Wo / W1 / W2)
__global__ __launch_bounds__(256, 2)
void gemm_tc1_kernel(const float* __restrict__ A, const float* __restrict__ Bp,
                     const float* __restrict__ bias, const float* __restrict__ res,
                     float* __restrict__ C, int M, int N, int Kd, int relu, int tout)
{
    extern __shared__ float sm[];
    const int tid  = threadIdx.x;
    const int wid  = tid >> 5;
    const int lane = tid & 31;
    const int grp  = lane >> 2;
    const int qr   = lane & 3;
    const int bm   = blockIdx.y << 7;
    const int bn   = blockIdx.x << 7;

    float acc[2][8][4];
#pragma unroll
    for (int mt = 0; mt < 2; mt++)
#pragma unroll
        for (int nt = 0; nt < 8; nt++)
#pragma unroll
            for (int r = 0; r < 4; r++) acc[mt][nt][r] = 0.f;

    gemm_core(sm, A, Bp, bm, bn, Kd, acc, tid, wid, lane, grp, qr);
    gemm_epilogue(acc, bias, res, C, bm, bn, N, relu, tout, wid, grp, qr);
}

// Merged QKV GEMM: one launch, grid (12, 128). sel = blockIdx.x >> 2 picks
// {Q, K, V}; math per tile is bitwise identical to three separate launches.
__global__ __launch_bounds__(256, 2)
void qkv_tc1_kernel(const float* __restrict__ A,
                    const float* __restrict__ wqp, const float* __restrict__ wkp,
                    const float* __restrict__ wvp,
                    const float* __restrict__ bq, const float* __restrict__ bk,
                    const float* __restrict__ bv,
                    float* __restrict__ q, float* __restrict__ kbuf,
                    float* __restrict__ vbuf)
{
    extern __shared__ float sm[];
    const int tid  = threadIdx.x;
    const int wid  = tid >> 5;
    const int lane = tid & 31;
    const int grp  = lane >> 2;
    const int qr   = lane & 3;
    const int sel  = blockIdx.x >> 2;
    const int bm   = blockIdx.y << 7;
    const int bn   = (blockIdx.x & 3) << 7;

    const float* Bp  = (sel == 0) ? wqp : (sel == 1) ? wkp : wvp;
    const float* bias = (sel == 0) ? bq : (sel == 1) ? bk : bv;
    float* C = (sel == 0) ? q : (sel == 1) ? kbuf : vbuf;

    float acc[2][8][4];
#pragma unroll
    for (int mt = 0; mt < 2; mt++)
#pragma unroll
        for (int nt = 0; nt < 8; nt++)
#pragma unroll
            for (int r = 0; r < 4; r++) acc[mt][nt][r] = 0.f;

    gemm_core(sm, A, Bp, bm, bn, D_DIM, acc, tid, wid, lane, grp, qr);
    gemm_epilogue(acc, bias, nullptr, C, bm, bn, D_DIM, 0, 1, wid, grp, qr);
}

// ===========================================================================
// Scores (1xTF32) + fused row-partial softmax stats (fp32 logits).
// ===========================================================================
#define SC_STAGE_FLOATS 9216
#define SC_SMEM_BYTES  (2 * SC_STAGE_FLOATS * 4)

__global__ __launch_bounds__(256, 2)
void tc_scores1_kernel(const float* __restrict__ q, const float* __restrict__ kt,
                       const float* __restrict__ gb, float* __restrict__ logits,
                       float* __restrict__ pm, float* __restrict__ ps)
{
    extern __shared__ float sm[];
    const int tid  = threadIdx.x;
    const int wid  = tid >> 5;
    const int lane = tid & 31;
    const int grp  = lane >> 2;
    const int qr   = lane & 3;
    const int h  = blockIdx.z;
    const int bt = h >> 3;
    const int kh = h & 7;
    const int bm = blockIdx.y << 7;
    const int bn = blockIdx.x << 7;
    const uint32_t sbase = smem_u32(sm);

    uint32_t soff[4];
    const float* gA[4];
    const float* gB[4];
#pragma unroll
    for (int i = 0; i < 4; i++) {
        int idx = i * 256 + tid;
        int row = idx >> 3;
        int c4  = idx & 7;
        soff[i] = (uint32_t)(row * 36 + c4 * 4) * 4u;
        gA[i] = q  + (size_t)(bt * 512 + bm + row) * 512 + kh * 64 + (c4 << 2);
        gB[i] = kt + (size_t)(bt * 512 + bn + row) * 512 + kh * 64 + (c4 << 2);
    }

#pragma unroll
    for (int i = 0; i < 4; i++) {
        CP_ASYNC16(sbase + soff[i], gA[i]);
        CP_ASYNC16(sbase + 4608u * 4u + soff[i], gB[i]);
    }
    CP_COMMIT();
#pragma unroll
    for (int i = 0; i < 4; i++) {
        CP_ASYNC16(sbase + SC_STAGE_FLOATS * 4u + soff[i], gA[i] + 32);
        CP_ASYNC16(sbase + SC_STAGE_FLOATS * 4u + 4608u * 4u + soff[i], gB[i] + 32);
    }
    CP_COMMIT();

    const int wm = (wid & 3) << 5;
    const int wn = (wid >> 2) << 6;

    float acc[2][8][4];
#pragma unroll
    for (int mt = 0; mt < 2; mt++)
#pragma unroll
        for (int nt = 0; nt < 8; nt++)
#pragma unroll
            for (int r = 0; r < 4; r++) acc[mt][nt][r] = 0.f;

#pragma unroll
    for (int c = 0; c < 2; c++) {
        if (c == 0) { CP_WAIT1(); } else { CP_WAIT0(); }
        __syncthreads();
        const float* Asb = sm + c * SC_STAGE_FLOATS;
        const float* Bsb = Asb + 4608;
#pragma unroll
        for (int ks = 0; ks < 4; ks++) {
            const float* Ac = Asb + ks * 8 + qr;
            const float* Bc = Bsb + ks * 8 + qr;
            uint32_t a_[2][4];
#pragma unroll
            for (int mt = 0; mt < 2; mt++) {
                int r0 = wm + mt * 16 + grp;
                a_[mt][0] = __float_as_uint(Ac[r0 * 36]);
                a_[mt][1] = __float_as_uint(Ac[(r0 + 8) * 36]);
                a_[mt][2] = __float_as_uint(Ac[r0 * 36 + 4]);
                a_[mt][3] = __float_as_uint(Ac[(r0 + 8) * 36 + 4]);
            }
            uint32_t b_[8][2];
#pragma unroll
            for (int nt = 0; nt < 8; nt++) {
                int rn = wn + nt * 8 + grp;
                b_[nt][0] = __float_as_uint(Bc[rn * 36]);
                b_[nt][1] = __float_as_uint(Bc[rn * 36 + 4]);
            }
#pragma unroll
            for (int mt = 0; mt < 2; mt++)
#pragma unroll
                for (int nt = 0; nt < 8; nt++)
                    MMA_TF32(acc[mt][nt], a_[mt][0], a_[mt][1], a_[mt][2], a_[mt][3],
                             b_[nt][0], b_[nt][1]);
        }
    }

    float* Lh = logits + (size_t)h * 512 * 512;
#pragma unroll
    for (int mt = 0; mt < 2; mt++) {
        const int gi = bm + wm + mt * 16 + grp;
#pragma unroll
        for (int nt = 0; nt < 8; nt++) {
            const int gj = bn + wn + nt * 8 + (qr << 1);
            float2 g0 = *(const float2*)(gb + (size_t)gi * 512 + gj);
            float2 g1 = *(const float2*)(gb + (size_t)(gi + 8) * 512 + gj);
            float v0 = fmaf(acc[mt][nt][0], 0.125f, g0.x);
            float v1 = fmaf(acc[mt][nt][1], 0.125f, g0.y);
            float v2 = fmaf(acc[mt][nt][2], 0.125f, g1.x);
            float v3 = fmaf(acc[mt][nt][3], 0.125f, g1.y);
            acc[mt][nt][0] = v0; acc[mt][nt][1] = v1;
            acc[mt][nt][2] = v2; acc[mt][nt][3] = v3;
            *(float2*)(Lh + (size_t)gi * 512 + gj)       = make_float2(v0, v1);
            *(float2*)(Lh + (size_t)(gi + 8) * 512 + gj) = make_float2(v2, v3);
        }
    }

    __syncthreads();
    float* smm = sm;
    float* sms = sm + 256;
    const int nw = wid >> 2;
#pragma unroll
    for (int mt = 0; mt < 2; mt++) {
#pragma unroll
        for (int half = 0; half < 2; half++) {
            float mx = -3.0e38f;
#pragma unroll
            for (int nt = 0; nt < 8; nt++)
                mx = fmaxf(mx, fmaxf(acc[mt][nt][half * 2], acc[mt][nt][half * 2 + 1]));
            mx = fmaxf(mx, __shfl_xor_sync(0xffffffffu, mx, 1));
            mx = fmaxf(mx, __shfl_xor_sync(0xffffffffu, mx, 2));
            float s = 0.f;
#pragma unroll
            for (int nt = 0; nt < 8; nt++) {
                s += __expf(acc[mt][nt][half * 2]     - mx);
                s += __expf(acc[mt][nt][half * 2 + 1] - mx);
            }
            s += __shfl_xor_sync(0xffffffffu, s, 1);
            s += __shfl_xor_sync(0xffffffffu, s, 2);
            if (qr == 0) {
                int r = (wid & 3) * 32 + mt * 16 + half * 8 + grp;
                smm[nw * 128 + r] = mx;
                sms[nw * 128 + r] = s;
            }
        }
    }
    __syncthreads();
    if (tid < 128) {
        float m0 = smm[tid], m1 = smm[128 + tid];
        float s0 = sms[tid], s1 = sms[128 + tid];
        float M = fmaxf(m0, m1);
        float S = s0 * __expf(m0 - M) + s1 * __expf(m1 - M);
        size_t pidx = ((size_t)h * 4 + blockIdx.x) * 512 + bm + tid;
        pm[pidx] = M;
        ps[pidx] = S;
    }
}

// ===========================================================================
// Row stat merge
// ===========================================================================
__global__ __launch_bounds__(256) void rowstat_kernel(
    const float* __restrict__ pm, const float* __restrict__ ps,
    float2* __restrict__ minv)
{
    int idx = blockIdx.x * 256 + threadIdx.x;
    if (idx >= H_HEADS * 512) return;
    int h = idx >> 9, row = idx & 511;
    float m[4], s[4];
#pragma unroll
    for (int jt = 0; jt < 4; jt++) {
        size_t p = ((size_t)h * 4 + jt) * 512 + row;
        m[jt] = pm[p]; s[jt] = ps[p];
    }
    float M = fmaxf(fmaxf(m[0], m[1]), fmaxf(m[2], m[3]));
    float S = s[0] * __expf(m[0] - M) + s[1] * __expf(m[1] - M)
            + s[2] * __expf(m[2] - M) + s[3] * __expf(m[3] - M);
    minv[idx] = make_float2(M, 1.0f / S);
}

// ===========================================================================
// AV (1xTF32) with in-staging softmax normalization (fp32 logits).
// ===========================================================================
#define AV1_STAGE_FLOATS 6912
#define AV1_SMEM_BYTES  (2 * AV1_STAGE_FLOATS * 4)

__global__ __launch_bounds__(256, 2)
void tc_av1_kernel(const float* __restrict__ attn, const float* __restrict__ vt,
                   const float2* __restrict__ minv, float* __restrict__ out)
{
    extern __shared__ float sm[];
    const int tid  = threadIdx.x;
    const int wid  = tid >> 5;
    const int lane = tid & 31;
    const int grp  = lane >> 2;
    const int qr   = lane & 3;
    const int h  = blockIdx.y;
    const int bt = h >> 3;
    const int kh = h & 7;
    const int bm = blockIdx.x << 7;

    int arow[4], ac4[4];
    float2 mi[4];
#pragma unroll
    for (int i = 0; i < 4; i++) {
        int idx = i * 256 + tid;
        arow[i] = idx >> 3;
        ac4[i]  = (idx & 7) << 2;
        mi[i] = minv[(size_t)h * 512 + bm + arow[i]];
    }
    int bk_[2], bn4[2];
#pragma unroll
    for (int i = 0; i < 2; i++) {
        int idx = i * 256 + tid;
        bk_[i] = idx >> 4;
        bn4[i] = (idx & 15) << 2;
    }

    const float* Abase = attn + (size_t)(h * 512 + bm) * 512;
    const float* Vbase = vt + (size_t)(bt * 512) * 512 + kh * 64;

    float4 ra[4], rb[2];
#pragma unroll
    for (int i = 0; i < 4; i++)
        ra[i] = *(const float4*)(Abase + (size_t)arow[i] * 512 + ac4[i]);
#pragma unroll
    for (int i = 0; i < 2; i++)
        rb[i] = *(const float4*)(Vbase + (size_t)bk_[i] * 512 + bn4[i]);

    const int wm = (wid & 3) << 5;
    const int wn = (wid >> 2) << 5;

    float acc[2][4][4];
#pragma unroll
    for (int mt = 0; mt < 2; mt++)
#pragma unroll
        for (int nt = 0; nt < 4; nt++)
#pragma unroll
            for (int r = 0; r < 4; r++) acc[mt][nt][r] = 0.f;

    for (int c = 0; c < 16; c++) {
        float* Asb = sm + (c & 1) * AV1_STAGE_FLOATS;
        float* Bsb = Asb + 4608;
#pragma unroll
        for (int i = 0; i < 4; i++) {
            float* p = Asb + arow[i] * 36 + ac4[i];
            p[0] = f2tf_f(__expf(ra[i].x - mi[i].x) * mi[i].y);
            p[1] = f2tf_f(__expf(ra[i].y - mi[i].x) * mi[i].y);
            p[2] = f2tf_f(__expf(ra[i].z - mi[i].x) * mi[i].y);
            p[3] = f2tf_f(__expf(ra[i].w - mi[i].x) * mi[i].y);
        }
#pragma unroll
        for (int i = 0; i < 2; i++) {
            Bsb[(bn4[i] + 0) * 36 + bk_[i]] = rb[i].x;
            Bsb[(bn4[i] + 1) * 36 + bk_[i]] = rb[i].y;
            Bsb[(bn4[i] + 2) * 36 + bk_[i]] = rb[i].z;
            Bsb[(bn4[i] + 3) * 36 + bk_[i]] = rb[i].w;
        }
        __syncthreads();
        if (c + 1 < 16) {
            const int k1 = (c + 1) << 5;
#pragma unroll
            for (int i = 0; i < 4; i++)
                ra[i] = *(const float4*)(Abase + (size_t)arow[i] * 512 + k1 + ac4[i]);
#pragma unroll
            for (int i = 0; i < 2; i++)
                rb[i] = *(const float4*)(Vbase + (size_t)(k1 + bk_[i]) * 512 + bn4[i]);
        }
#pragma unroll
        for (int ks = 0; ks < 4; ks++) {
            const float* Ac = Asb + ks * 8 + qr;
            const float* Bc = Bsb + ks * 8 + qr;
            uint32_t a_[2][4];
#pragma unroll
            for (int mt = 0; mt < 2; mt++) {
                int r0 = wm + mt * 16 + grp;
                a_[mt][0] = __float_as_uint(Ac[r0 * 36]);
                a_[mt][1] = __float_as_uint(Ac[(r0 + 8) * 36]);
                a_[mt][2] = __float_as_uint(Ac[r0 * 36 + 4]);
                a_[mt][3] = __float_as_uint(Ac[(r0 + 8) * 36 + 4]);
            }
            uint32_t b_[4][2];
#pragma unroll
            for (int nt = 0; nt < 4; nt++) {
                int rn = wn + nt * 8 + grp;
                b_[nt][0] = __float_as_uint(Bc[rn * 36]);
                b_[nt][1] = __float_as_uint(Bc[rn * 36 + 4]);
            }
#pragma unroll
            for (int mt = 0; mt < 2; mt++)
#pragma unroll
                for (int nt = 0; nt < 4; nt++)
                    MMA_TF32(acc[mt][nt], a_[mt][0], a_[mt][1], a_[mt][2], a_[mt][3],
                             b_[nt][0], b_[nt][1]);
        }
        __syncthreads();
    }

#pragma unroll
    for (int mt = 0; mt < 2; mt++) {
        const int r0 = bt * 512 + bm + wm + mt * 16 + grp;
#pragma unroll
        for (int nt = 0; nt < 4; nt++) {
            const int col = kh * 64 + wn + nt * 8 + (qr << 1);
            *(float2*)(out + (size_t)r0 * 512 + col) =
                make_float2(f2tf_f(acc[mt][nt][0]), f2tf_f(acc[mt][nt][1]));
            *(float2*)(out + (size_t)(r0 + 8) * 512 + col) =
                make_float2(f2tf_f(acc[mt][nt][2]), f2tf_f(acc[mt][nt][3]));
        }
    }
}

// ---------------------------------------------------------------------------
// Graph bias precompute
// ---------------------------------------------------------------------------
__global__ __launch_bounds__(256) void bias_kernel(
    const float* __restrict__ E, const float* __restrict__ lap,
    const float* __restrict__ alphap, const float* __restrict__ betap,
    float* __restrict__ gb)
{
    __shared__ __align__(16) float ei[64];
    __shared__ float reda[8];
    __shared__ float redb[8];
    int i = blockIdx.x;
    int tid = threadIdx.x;
    if (tid < 16) ((float4*)ei)[tid] = ((const float4*)(E + (size_t)i * 64))[tid];
    __syncthreads();

    int j0 = tid, j1 = tid + 256;
    const float* e0 = E + (size_t)j0 * 64;
    const float* e1 = E + (size_t)j1 * 64;
    float r0 = 0.f, r1 = 0.f;
#pragma unroll
    for (int e = 0; e < 64; e += 4) {
        float4 a = *(const float4*)(ei + e);
        float4 u = *(const float4*)(e0 + e);
        float4 w = *(const float4*)(e1 + e);
        r0 += a.x * u.x + a.y * u.y + a.z * u.z + a.w * u.w;
        r1 += a.x * w.x + a.y * w.y + a.z * w.z + a.w * w.w;
    }
    r0 = fmaxf(r0, 0.f);
    r1 = fmaxf(r1, 0.f);

    float mx = fmaxf(r0, r1);
#pragma unroll
    for (int o = 16; o; o >>= 1) mx = fmaxf(mx, __shfl_xor_sync(0xffffffffu, mx, o));
    if ((tid & 31) == 0) reda[tid >> 5] = mx;
    __syncthreads();
    mx = fmaxf(fmaxf(fmaxf(reda[0], reda[1]), fmaxf(reda[2], reda[3])),
               fmaxf(fmaxf(reda[4], reda[5]), fmaxf(reda[6], reda[7])));

    float ex0 = __expf(r0 - mx), ex1 = __expf(r1 - mx);
    float s = ex0 + ex1;
#pragma unroll
    for (int o = 16; o; o >>= 1) s += __shfl_xor_sync(0xffffffffu, s, o);
    if ((tid & 31) == 0) redb[tid >> 5] = s;
    __syncthreads();
    s = redb[0] + redb[1] + redb[2] + redb[3] + redb[4] + redb[5] + redb[6] + redb[7];
    float inv = 1.0f / s;

    float alpha = *alphap, beta = *betap;
    float lp0 = lap[(size_t)i * 512 + j0];
    float lp1 = lap[(size_t)i * 512 + j1];
    float m0 = (lp0 != 0.f) ? 0.f : -1e9f;
    float m1 = (lp1 != 0.f) ? 0.f : -1e9f;
    gb[(size_t)i * 512 + j0] = alpha * ex0 * inv + beta * lp0 + m0;
    gb[(size_t)i * 512 + j1] = alpha * ex1 * inv + beta * lp1 + m1;
}

// ---------------------------------------------------------------------------
// LayerNorm over D=512, one warp per row, tf32-truncated output.
// ---------------------------------------------------------------------------
__global__ __launch_bounds__(256) void ln_kernel(
    const float* __restrict__ X, const float* __restrict__ g,
    const float* __restrict__ b, float* __restrict__ Y, int rows)
{
    int gw = (blockIdx.x * 256 + threadIdx.x) >> 5;
    if (gw >= rows) return;
    int lane = threadIdx.x & 31;
    const float* xr = X + (size_t)gw * 512;
    float* yr = Y + (size_t)gw * 512;
    float4 v[4];
    float s = 0.f, ss = 0.f;
#pragma unroll
    for (int w = 0; w < 4; w++) {
        v[w] = *(const float4*)(xr + w * 128 + lane * 4);
        s += v[w].x + v[w].y + v[w].z + v[w].w;
        ss += v[w].x * v[w].x + v[w].y * v[w].y + v[w].z * v[w].z + v[w].w * v[w].w;
    }
#pragma unroll
    for (int o = 16; o; o >>= 1) {
        s += __shfl_xor_sync(0xffffffffu, s, o);
        ss += __shfl_xor_sync(0xffffffffu, ss, o);
    }
    float mean = s * (1.0f / 512.0f);
    float var = ss * (1.0f / 512.0f) - mean * mean;
    float rstd = rsqrtf(var + 1e-5f);
#pragma unroll
    for (int w = 0; w < 4; w++) {
        int c = w * 128 + lane * 4;
        float4 gg = *(const float4*)(g + c);
        float4 bb = *(const float4*)(b + c);
        float4 o;
        o.x = f2tf_f((v[w].x - mean) * rstd * gg.x + bb.x);
        o.y = f2tf_f((v[w].y - mean) * rstd * gg.y + bb.y);
        o.z = f2tf_f((v[w].z - mean) * rstd * gg.z + bb.z);
        o.w = f2tf_f((v[w].w - mean) * rstd * gg.w + bb.w);
        *(float4*)(yr + c) = o;
    }
}

// ---------------------------------------------------------------------------
// Host launcher
// ---------------------------------------------------------------------------
extern "C" void kernel_launch(void* const* d_in, const int* in_sizes, int n_in,
                              void* d_out, int out_size)
{
    const float* x    = (const float*)d_in[0];
    const float* lap  = (const float*)d_in[1];
    const float* emb  = (const float*)d_in[2];
    const float* Wq   = (const float*)d_in[3];
    const float* bq   = (const float*)d_in[4];
    const float* Wk   = (const float*)d_in[5];
    const float* bk   = (const float*)d_in[6];
    const float* Wv   = (const float*)d_in[7];
    const float* bv   = (const float*)d_in[8];
    const float* ln1g = (const float*)d_in[9];
    const float* ln1b = (const float*)d_in[10];
    const float* ln2g = (const float*)d_in[11];
    const float* ln2b = (const float*)d_in[12];
    const float* alpha = (const float*)d_in[13];
    const float* beta  = (const float*)d_in[14];
    const float* Wo   = (const float*)d_in[15];
    const float* bo   = (const float*)d_in[16];
    const float* W1   = (const float*)d_in[17];
    const float* b1   = (const float*)d_in[18];
    const float* W2   = (const float*)d_in[19];
    const float* b2   = (const float*)d_in[20];
    float* out = (float*)d_out;

    float* base = nullptr;
    cudaGetSymbolAddress((void**)&base, g_scratch);
    float* xn     = base + OFF_XN;
    float* q      = base + OFF_Q;
    float* kbuf   = base + OFF_K;
    float* vbuf   = base + OFF_V;
    float* ao     = base + OFF_AO;
    float* x1     = base + OFF_X1;
    float* hin    = base + OFF_HIN;
    float* hbuf   = base + OFF_HB;
    float* logits = base + OFF_LOG;
    float* gb     = base + OFF_GB;
    float* wqp = base + OFF_WQT;
    float* wkp = base + OFF_WKT;
    float* wvp = base + OFF_WVT;
    float* wop = base + OFF_WOT;
    float* w1p = base + OFF_W1T;
    float* w2p = base + OFF_W2T;
    float* pm  = base + OFF_PM;
    float* ps  = base + OFF_PS;
    float2* minv = (float2*)(base + OFF_MINV);

    static bool attr_done = false;
    if (!attr_done) {
        cudaFuncSetAttribute(gemm_tc1_kernel,
                             cudaFuncAttributeMaxDynamicSharedMemorySize, G1_SMEM_BYTES);
        cudaFuncSetAttribute(qkv_tc1_kernel,
                             cudaFuncAttributeMaxDynamicSharedMemorySize, G1_SMEM_BYTES);
        cudaFuncSetAttribute(tc_scores1_kernel,
                             cudaFuncAttributeMaxDynamicSharedMemorySize, SC_SMEM_BYTES);
        cudaFuncSetAttribute(tc_av1_kernel,
                             cudaFuncAttributeMaxDynamicSharedMemorySize, AV1_SMEM_BYTES);
        attr_done = true;
    }

    // 0. all-weight tf32 truncate + fragment pack in one launch
    pack_all_kernel<<<6144, 256>>>(Wq, Wk, Wv, Wo, W1, W2,
                                   wqp, wkp, wvp, wop, w1p, w2p);

    // 1. graph bias
    bias_kernel<<<512, 256>>>(emb, lap, alpha, beta, gb);

    // 2. LN1 (tf32-truncated)
    ln_kernel<<<R_ROWS / 8, 256>>>(x, ln1g, ln1b, xn, R_ROWS);

    // 3. QKV projections merged into ONE launch (grid 12x128) — single tail
    qkv_tc1_kernel<<<dim3(12, R_ROWS / 128), 256, G1_SMEM_BYTES>>>(
        xn, wqp, wkp, wvp, bq, bk, bv, q, kbuf, vbuf);

    // 4. scores + bias + fused row partials
    tc_scores1_kernel<<<dim3(4, 4, H_HEADS), 256, SC_SMEM_BYTES>>>(
        q, kbuf, gb, logits, pm, ps);

    // 5. merge row stats
    rowstat_kernel<<<512, 256>>>(pm, ps, minv);

    // 6. attn @ V with in-staging softmax normalization
    tc_av1_kernel<<<dim3(4, H_HEADS), 256, AV1_SMEM_BYTES>>>(logits, vbuf, minv, ao);

    // 7. output projection + residual (1x, packed-B)
    dim3 gq(D_DIM / 128, R_ROWS / 128);
    gemm_tc1_kernel<<<gq, 256, G1_SMEM_BYTES>>>(
        ao, wop, bo, x, x1, R_ROWS, D_DIM, D_DIM, 0, 0);

    // 8. LN2 (tf32-truncated)
    ln_kernel<<<R_ROWS / 8, 256>>>(x1, ln2g, ln2b, hin, R_ROWS);

    // 9. FF up (1x, packed-B, relu, truncated output)
    gemm_tc1_kernel<<<dim3(DFF / 128, R_ROWS / 128), 256, G1_SMEM_BYTES>>>(
        hin, w1p, b1, nullptr, hbuf, R_ROWS, DFF, D_DIM, 1, 1);

    // 10. FF down + residual (1x, packed-B)
    gemm_tc1_kernel<<<dim3(D_DIM / 128, R_ROWS / 128), 256, G1_SMEM_BYTES>>>(
        hbuf, w2p, b2, x1, out, R_ROWS, D_DIM, DFF, 0, 0);
}